// round 17
// baseline (speedup 1.0000x reference)
#include <cuda_runtime.h>
#include <cuda_fp16.h>
#include <math.h>
#include <cstdint>

#define NNODES 50000
#define NEDGES 800000
#define NBLK 13

// ---------------------------------------------------------------------------
// Scratch
// ---------------------------------------------------------------------------
__device__ __align__(16) __half g_A[(size_t)NNODES * 192];     // edge gather out (fp16)
__device__ __align__(16) __half g_B[(size_t)NNODES * 128];     // node gather out (fp16)
__device__ __align__(16) __half g_Whi[9][192 * 192];
__device__ __align__(16) __half g_Wlo[9][192 * 192];
__device__ __align__(16) __half g_actA[(size_t)NNODES * 192];  // edge activations (fp16)
__device__ __align__(16) __half g_actB[(size_t)NNODES * 128];  // x pad / n1 (fp16)
__device__ __align__(16) __half g_actC[(size_t)NNODES * 128];  // node reparam (fp16)
__device__ float g_dinv[NNODES];
__device__ int   g_row[NEDGES];
__device__ int   g_col[NEDGES];
__device__ int   g_ideg[NNODES];
__device__ int   g_off[NNODES + 1];
__device__ int   g_cursor[NNODES];
__device__ int2  g_ecsr[NEDGES];
__device__ int   g_bsum[32];
__device__ unsigned g_flag32;   // monotone across replays (same input -> same value)

// ---------------------------------------------------------------------------
// PTX helpers (sm_103-safe)
// ---------------------------------------------------------------------------
__device__ __forceinline__ unsigned s2u(const void* p) {
    return (unsigned)__cvta_generic_to_shared(p);
}
__device__ __forceinline__ void cpa16(unsigned dst, const void* src, bool p) {
    asm volatile("cp.async.cg.shared.global [%0], [%1], 16, %2;"
                 :: "r"(dst), "l"(src), "r"(p ? 16 : 0));
}
#define CP_COMMIT() asm volatile("cp.async.commit_group;")
template <int N>
__device__ __forceinline__ void cp_wait() {
    asm volatile("cp.async.wait_group %0;" :: "n"(N) : "memory");
}
__device__ __forceinline__ uint32_t lds32(uint32_t a) {
    uint32_t v;
    asm volatile("ld.shared.b32 %0,[%1];" : "=r"(v) : "r"(a));
    return v;
}
__device__ __forceinline__ void mma16816(float* c, const uint32_t* a,
                                         const uint32_t* b) {
    asm volatile(
        "mma.sync.aligned.m16n8k16.row.col.f32.f16.f16.f32 "
        "{%0,%1,%2,%3}, {%4,%5,%6,%7}, {%8,%9}, {%0,%1,%2,%3};"
        : "+f"(c[0]), "+f"(c[1]), "+f"(c[2]), "+f"(c[3])
        : "r"(a[0]), "r"(a[1]), "r"(a[2]), "r"(a[3]), "r"(b[0]), "r"(b[1]));
}
__device__ __forceinline__ uint32_t hfp(float a, float b) {
    __half2 t;
    t.x = __float2half_rn(a);
    t.y = __float2half_rn(b);
    return *reinterpret_cast<uint32_t*>(&t);
}
__device__ __forceinline__ float4 h4(uint2 u) {
    __half2 a = *reinterpret_cast<__half2*>(&u.x);
    __half2 b = *reinterpret_cast<__half2*>(&u.y);
    float2 fa = __half22float2(a);
    float2 fb = __half22float2(b);
    return make_float4(fa.x, fa.y, fb.x, fb.y);
}

// ---------------------------------------------------------------------------
// Prep kernels
// ---------------------------------------------------------------------------
__global__ void k_prep1() {
    int i = blockIdx.x * blockDim.x + threadIdx.x;
    if (i < NNODES) g_ideg[i] = 0;
}

// Reads pairs of 32-bit words coalesced; ORs the odd (high) words.
__global__ void k_detect(const uint2* __restrict__ w) {
    unsigned v = 0;
    for (int i = blockIdx.x * blockDim.x + threadIdx.x; i < NEDGES;
         i += gridDim.x * blockDim.x)
        v |= w[i].y;
    #pragma unroll
    for (int o = 16; o; o >>= 1) v |= __shfl_xor_sync(0xFFFFFFFFu, v, o);
    if ((threadIdx.x & 31) == 0 && v) atomicOr(&g_flag32, 1u);
}

__global__ void k_convert(const void* __restrict__ ei) {
    int e = blockIdx.x * blockDim.x + threadIdx.x;
    if (e >= NEDGES) return;
    int r, c;
    if (g_flag32 == 0u) {
        const long long* ll = (const long long*)ei;
        r = (int)ll[e];
        c = (int)ll[NEDGES + e];
    } else {
        const int* q = (const int*)ei;
        r = q[e];
        c = q[NEDGES + e];
    }
    g_row[e] = r;
    g_col[e] = c;
    atomicAdd(&g_ideg[c], 1);
}

// scanA: per-block sums; also computes dinv
__global__ __launch_bounds__(1024) void k_scanA() {
    __shared__ int sh[32];
    int b = blockIdx.x, t = threadIdx.x;
    int base = b * 4096 + t * 4;
    int s = 0;
    #pragma unroll
    for (int j = 0; j < 4; j++) {
        int i = base + j;
        if (i < NNODES) {
            int dv = g_ideg[i];
            s += dv;
            g_dinv[i] = rsqrtf((float)dv + 1.0f);
        }
    }
    #pragma unroll
    for (int o = 16; o; o >>= 1) s += __shfl_xor_sync(0xFFFFFFFFu, s, o);
    if ((t & 31) == 0) sh[t >> 5] = s;
    __syncthreads();
    if (t < 32) {
        int x = sh[t];
        #pragma unroll
        for (int o = 16; o; o >>= 1) x += __shfl_xor_sync(0xFFFFFFFFu, x, o);
        if (t == 0) g_bsum[b] = x;
    }
}

// scanC: full exclusive scan; block prefix computed inline (scanB folded in)
__global__ __launch_bounds__(1024) void k_scanC() {
    __shared__ int sh[1024];
    __shared__ int pre;
    int b = blockIdx.x, t = threadIdx.x;
    if (t == 0) {
        int p = 0;
        for (int i = 0; i < b; i++) p += g_bsum[i];
        pre = p;
    }
    int base = b * 4096 + t * 4;
    int v[4];
    int s = 0;
    #pragma unroll
    for (int j = 0; j < 4; j++) {
        int i = base + j;
        v[j] = (i < NNODES) ? g_ideg[i] : 0;
        s += v[j];
    }
    sh[t] = s;
    __syncthreads();
    #pragma unroll
    for (int o = 1; o < 1024; o <<= 1) {
        int tmp = (t >= o) ? sh[t - o] : 0;
        __syncthreads();
        sh[t] += tmp;
        __syncthreads();
    }
    int excl = sh[t] - s + pre;
    #pragma unroll
    for (int j = 0; j < 4; j++) {
        int i = base + j;
        if (i < NNODES) { g_off[i] = excl; g_cursor[i] = excl; }
        excl += v[j];
    }
    if (b == 0 && t == 0) g_off[NNODES] = NEDGES;
}

__global__ void k_fill() {
    int e = blockIdx.x * blockDim.x + threadIdx.x;
    if (e >= NEDGES) return;
    int r = g_row[e], c = g_col[e];
    float cf = g_dinv[r] * g_dinv[c];
    int pos = atomicAdd(&g_cursor[c], 1);
    g_ecsr[pos] = make_int2(r, __float_as_int(cf));
}

// All 9 weight transposes + fp16 splits in one launch.
struct WSet { const float* w[9]; int K[9]; int M[9]; };
__global__ void k_wsplit_all(WSet ws, __half* __restrict__ hiB,
                             __half* __restrict__ loB) {
    int slab = blockIdx.y;
    int idx = blockIdx.x * blockDim.x + threadIdx.x;
    if (idx >= 192 * 192) return;
    int n = idx / 192, k = idx % 192;
    int K = ws.K[slab], M = ws.M[slab];
    float v = (k < K && n < M) ? ws.w[slab][(size_t)k * M + n] : 0.0f;
    __half h = __float2half_rn(v);
    size_t o = (size_t)slab * 192 * 192 + idx;
    hiB[o] = h;
    loB[o] = __float2half_rn(v - __half2float(h));
}

// Pad x [N,96] fp32 -> [N,128] fp16
__global__ void k_padx(const float* __restrict__ x, __half* __restrict__ o) {
    int i = blockIdx.x * blockDim.x + threadIdx.x;
    if (i >= NNODES * 128) return;
    int n = i >> 7, c = i & 127;
    o[i] = (c < 96) ? __float2half_rn(x[n * 96 + c]) : __half(0.0f);
}

// ---------------------------------------------------------------------------
// Gather (fp16 in via uint2, fp32 accum, fp16 out). One warp per node.
// KPAD=128: exactly 1 uint2 (4 halves) per lane; 192: 2 units (48 of 64).
// ---------------------------------------------------------------------------
template <int KPAD>
__global__ __launch_bounds__(256) void k_gather(const uint2* __restrict__ in,
                                                uint2* __restrict__ outw) {
    constexpr int NVU = KPAD / 4;          // uint2 per row (32 or 48)
    constexpr int NIT = (NVU + 31) / 32;   // 1 or 2
    int node = blockIdx.x * 8 + (threadIdx.x >> 5);
    if (node >= NNODES) return;
    int lane = threadIdx.x & 31;

    float d = g_dinv[node];
    float dd = d * d;

    float4 acc[NIT];
    #pragma unroll
    for (int v = 0; v < NIT; v++) {
        int id = lane + 32 * v;
        if (id < NVU) {
            float4 t = h4(in[(size_t)node * NVU + id]);
            acc[v] = make_float4(t.x * dd, t.y * dd, t.z * dd, t.w * dd);
        } else acc[v] = make_float4(0.f, 0.f, 0.f, 0.f);
    }

    int s = g_off[node];
    int e = g_off[node + 1];
    int i = s;
    for (; i + 3 < e; i += 4) {
        int2 p0 = g_ecsr[i];
        int2 p1 = g_ecsr[i + 1];
        int2 p2 = g_ecsr[i + 2];
        int2 p3 = g_ecsr[i + 3];
        float c0 = __int_as_float(p0.y), c1 = __int_as_float(p1.y);
        float c2 = __int_as_float(p2.y), c3 = __int_as_float(p3.y);
        #pragma unroll
        for (int v = 0; v < NIT; v++) {
            int id = lane + 32 * v;
            if (id < NVU) {
                float4 a0 = h4(in[(size_t)p0.x * NVU + id]);
                float4 a1 = h4(in[(size_t)p1.x * NVU + id]);
                float4 a2 = h4(in[(size_t)p2.x * NVU + id]);
                float4 a3 = h4(in[(size_t)p3.x * NVU + id]);
                acc[v].x += a0.x * c0; acc[v].y += a0.y * c0;
                acc[v].z += a0.z * c0; acc[v].w += a0.w * c0;
                acc[v].x += a1.x * c1; acc[v].y += a1.y * c1;
                acc[v].z += a1.z * c1; acc[v].w += a1.w * c1;
                acc[v].x += a2.x * c2; acc[v].y += a2.y * c2;
                acc[v].z += a2.z * c2; acc[v].w += a2.w * c2;
                acc[v].x += a3.x * c3; acc[v].y += a3.y * c3;
                acc[v].z += a3.z * c3; acc[v].w += a3.w * c3;
            }
        }
    }
    for (; i < e; i++) {
        int2 p = g_ecsr[i];
        float c0 = __int_as_float(p.y);
        #pragma unroll
        for (int v = 0; v < NIT; v++) {
            int id = lane + 32 * v;
            if (id < NVU) {
                float4 a = h4(in[(size_t)p.x * NVU + id]);
                acc[v].x += a.x * c0; acc[v].y += a.y * c0;
                acc[v].z += a.z * c0; acc[v].w += a.w * c0;
            }
        }
    }
    #pragma unroll
    for (int v = 0; v < NIT; v++) {
        int id = lane + 32 * v;
        if (id < NVU) {
            uint2 p;
            p.x = hfp(acc[v].x, acc[v].y);
            p.y = hfp(acc[v].z, acc[v].w);
            outw[(size_t)node * NVU + id] = p;
        }
    }
}

// ---------------------------------------------------------------------------
// mma.sync GEMM: A plain fp16, W split hi/lo. 2 MMAs per fragment.
// Block 256 thr, tile 128x64, warp 32x32, BK=32 double-buffered.
// ---------------------------------------------------------------------------
#define RS 80
#define ASZ (128 * RS)
#define BSZ (64 * RS)

__global__ __launch_bounds__(256, 3) void k_mgemm(
    const __half* __restrict__ A, int kpad,
    const __half* __restrict__ Wh, const __half* __restrict__ Wl,
    const float* __restrict__ bias, void* __restrict__ out, int ldc,
    int M, int nk, int mode, int half_out, int rows)
{
    extern __shared__ char sm[];
    uint32_t base = s2u(sm);
    const int STRIDE = ASZ + 2 * BSZ;
    int tid = threadIdx.x;
    int wid = tid >> 5, lane = tid & 31;
    int g = lane >> 2, t = lane & 3;
    int wm = wid & 3, wn = wid >> 2;
    int r0 = blockIdx.y * 128;
    int c0 = blockIdx.x * 64;

    auto loadT = [&](int b, int k0) {
        uint32_t ba = base + b * STRIDE;
        #pragma unroll
        for (int i = 0; i < 2; i++) {
            int it = tid + i * 256;
            int m = it >> 2, c = it & 3;
            int gr = r0 + m;
            bool ok = (gr < rows);
            size_t so = (size_t)(ok ? gr : 0) * kpad + k0 + c * 8;
            cpa16(ba + m * RS + c * 16, A + so, ok);
        }
        {
            int n = tid >> 2, c = tid & 3;
            size_t so = (size_t)(c0 + n) * 192 + k0 + c * 8;
            uint32_t dd = ba + ASZ + n * RS + c * 16;
            cpa16(dd, Wh + so, true);
            cpa16(dd + BSZ, Wl + so, true);
        }
        CP_COMMIT();
    };

    loadT(0, 0);

    float acc[2][4][4];
    #pragma unroll
    for (int i = 0; i < 2; i++)
        #pragma unroll
        for (int j = 0; j < 4; j++)
            #pragma unroll
            for (int q = 0; q < 4; q++) acc[i][j][q] = 0.0f;

    for (int it = 0; it < nk; it++) {
        int b = it & 1;
        if (it + 1 < nk) { loadT(b ^ 1, (it + 1) * 32); cp_wait<1>(); }
        else cp_wait<0>();
        __syncthreads();
        uint32_t ba = base + b * STRIDE;
        uint32_t aB = ba + (wm * 32 + g) * RS + t * 4;
        uint32_t bB = ba + ASZ + (wn * 32 + g) * RS + t * 4;
        #pragma unroll
        for (int kc = 0; kc < 2; kc++) {
            uint32_t ah[2][4];
            #pragma unroll
            for (int ms = 0; ms < 2; ms++) {
                uint32_t a0 = aB + ms * (16 * RS) + kc * 32;
                ah[ms][0] = lds32(a0);
                ah[ms][1] = lds32(a0 + 8 * RS);
                ah[ms][2] = lds32(a0 + 16);
                ah[ms][3] = lds32(a0 + 8 * RS + 16);
            }
            #pragma unroll
            for (int ns = 0; ns < 4; ns++) {
                uint32_t b0 = bB + ns * (8 * RS) + kc * 32;
                uint32_t bh[2], bl[2];
                bh[0] = lds32(b0);
                bh[1] = lds32(b0 + 16);
                bl[0] = lds32(b0 + BSZ);
                bl[1] = lds32(b0 + BSZ + 16);
                #pragma unroll
                for (int ms = 0; ms < 2; ms++) {
                    mma16816(acc[ms][ns], ah[ms], bh);
                    mma16816(acc[ms][ns], ah[ms], bl);
                }
            }
        }
        __syncthreads();
    }

    #pragma unroll
    for (int ms = 0; ms < 2; ms++) {
        #pragma unroll
        for (int h = 0; h < 2; h++) {
            int r = r0 + wm * 32 + ms * 16 + h * 8 + g;
            if (r >= rows) continue;
            #pragma unroll
            for (int ns = 0; ns < 4; ns++) {
                int cc = c0 + wn * 32 + ns * 8 + 2 * t;
                if (cc >= ldc) continue;
                float v0 = acc[ms][ns][h * 2 + 0];
                float v1 = acc[ms][ns][h * 2 + 1];
                if (cc < M) {
                    v0 += bias[cc];
                    if (mode == 1) v0 = fmaxf(v0, 0.0f);
                    else if (mode == 2) v0 = 1.0f / (1.0f + expf(-v0));
                } else v0 = 0.0f;
                if (cc + 1 < M) {
                    v1 += bias[cc + 1];
                    if (mode == 1) v1 = fmaxf(v1, 0.0f);
                    else if (mode == 2) v1 = 1.0f / (1.0f + expf(-v1));
                } else v1 = 0.0f;
                if (half_out) {
                    *(uint32_t*)((__half*)out + (size_t)r * ldc + cc) = hfp(v0, v1);
                } else {
                    float2 st; st.x = v0; st.y = v1;
                    *(float2*)((float*)out + (size_t)r * ldc + cc) = st;
                }
            }
        }
    }
}

// ---------------------------------------------------------------------------
// Dual mma.sync GEMM: out = mu + eps*exp(ls)/10 (fp16 out), 4 MMAs/frag.
// ---------------------------------------------------------------------------
__global__ __launch_bounds__(256, 3) void k_mgemm_dual(
    const __half* __restrict__ A, int kpad,
    const __half* __restrict__ W1h, const __half* __restrict__ W1l,
    const __half* __restrict__ W2h, const __half* __restrict__ W2l,
    const float* __restrict__ b1, const float* __restrict__ b2,
    const float* __restrict__ eps, int lde,
    __half* __restrict__ out, int ldc, int M, int nk, int rows)
{
    extern __shared__ char sm[];
    uint32_t base = s2u(sm);
    const int STRIDE = ASZ + 4 * BSZ;
    int tid = threadIdx.x;
    int wid = tid >> 5, lane = tid & 31;
    int g = lane >> 2, t = lane & 3;
    int wm = wid & 3, wn = wid >> 2;
    int r0 = blockIdx.y * 128;
    int c0 = blockIdx.x * 64;

    auto loadT = [&](int b, int k0) {
        uint32_t ba = base + b * STRIDE;
        #pragma unroll
        for (int i = 0; i < 2; i++) {
            int it = tid + i * 256;
            int m = it >> 2, c = it & 3;
            int gr = r0 + m;
            bool ok = (gr < rows);
            size_t so = (size_t)(ok ? gr : 0) * kpad + k0 + c * 8;
            cpa16(ba + m * RS + c * 16, A + so, ok);
        }
        {
            int n = tid >> 2, c = tid & 3;
            size_t so = (size_t)(c0 + n) * 192 + k0 + c * 8;
            uint32_t dd = ba + ASZ + n * RS + c * 16;
            cpa16(dd, W1h + so, true);
            cpa16(dd + BSZ, W1l + so, true);
            cpa16(dd + 2 * BSZ, W2h + so, true);
            cpa16(dd + 3 * BSZ, W2l + so, true);
        }
        CP_COMMIT();
    };

    loadT(0, 0);

    float ac1[2][4][4], ac2[2][4][4];
    #pragma unroll
    for (int i = 0; i < 2; i++)
        #pragma unroll
        for (int j = 0; j < 4; j++)
            #pragma unroll
            for (int q = 0; q < 4; q++) { ac1[i][j][q] = 0.0f; ac2[i][j][q] = 0.0f; }

    for (int it = 0; it < nk; it++) {
        int b = it & 1;
        if (it + 1 < nk) { loadT(b ^ 1, (it + 1) * 32); cp_wait<1>(); }
        else cp_wait<0>();
        __syncthreads();
        uint32_t ba = base + b * STRIDE;
        uint32_t aB = ba + (wm * 32 + g) * RS + t * 4;
        uint32_t bB = ba + ASZ + (wn * 32 + g) * RS + t * 4;
        #pragma unroll
        for (int kc = 0; kc < 2; kc++) {
            uint32_t ah[2][4];
            #pragma unroll
            for (int ms = 0; ms < 2; ms++) {
                uint32_t a0 = aB + ms * (16 * RS) + kc * 32;
                ah[ms][0] = lds32(a0);
                ah[ms][1] = lds32(a0 + 8 * RS);
                ah[ms][2] = lds32(a0 + 16);
                ah[ms][3] = lds32(a0 + 8 * RS + 16);
            }
            #pragma unroll
            for (int ns = 0; ns < 4; ns++) {
                uint32_t b0 = bB + ns * (8 * RS) + kc * 32;
                uint32_t b1h[2], b1l[2], b2h[2], b2l[2];
                b1h[0] = lds32(b0);            b1h[1] = lds32(b0 + 16);
                b1l[0] = lds32(b0 + BSZ);      b1l[1] = lds32(b0 + BSZ + 16);
                b2h[0] = lds32(b0 + 2 * BSZ);  b2h[1] = lds32(b0 + 2 * BSZ + 16);
                b2l[0] = lds32(b0 + 3 * BSZ);  b2l[1] = lds32(b0 + 3 * BSZ + 16);
                #pragma unroll
                for (int ms = 0; ms < 2; ms++) {
                    mma16816(ac1[ms][ns], ah[ms], b1h);
                    mma16816(ac1[ms][ns], ah[ms], b1l);
                    mma16816(ac2[ms][ns], ah[ms], b2h);
                    mma16816(ac2[ms][ns], ah[ms], b2l);
                }
            }
        }
        __syncthreads();
    }

    #pragma unroll
    for (int ms = 0; ms < 2; ms++) {
        #pragma unroll
        for (int h = 0; h < 2; h++) {
            int r = r0 + wm * 32 + ms * 16 + h * 8 + g;
            if (r >= rows) continue;
            #pragma unroll
            for (int ns = 0; ns < 4; ns++) {
                int cc = c0 + wn * 32 + ns * 8 + 2 * t;
                if (cc >= ldc) continue;
                float v0 = 0.0f, v1 = 0.0f;
                if (cc < M) {
                    float mu = ac1[ms][ns][h * 2 + 0] + b1[cc];
                    float ls = ac2[ms][ns][h * 2 + 0] + b2[cc];
                    v0 = mu + eps[(size_t)r * lde + cc] * expf(ls) * 0.1f;
                }
                if (cc + 1 < M) {
                    float mu = ac1[ms][ns][h * 2 + 1] + b1[cc + 1];
                    float ls = ac2[ms][ns][h * 2 + 1] + b2[cc + 1];
                    v1 = mu + eps[(size_t)r * lde + cc + 1] * expf(ls) * 0.1f;
                }
                *(uint32_t*)(out + (size_t)r * ldc + cc) = hfp(v0, v1);
            }
        }
    }
}

// ---------------------------------------------------------------------------
// Host side
// ---------------------------------------------------------------------------
static __half *hA, *hB, *hWhi, *hWlo;
static __half *hactA, *hactB, *hactC;

static void prop(const __half* in, int KPAD, __half* outp, cudaStream_t st) {
    int blocks = (NNODES + 7) / 8;
    uint2* o = (uint2*)outp;
    if (KPAD == 128)
        k_gather<128><<<blocks, 256, 0, st>>>((const uint2*)in, o);
    else
        k_gather<192><<<blocks, 256, 0, st>>>((const uint2*)in, o);
}

static void mm(const __half* a, int kpad, int widx, int K, const float* bias,
               void* out, int ldc, int M, int mode, int half_out,
               cudaStream_t st) {
    int nk = (K + 31) / 32;
    dim3 grid((ldc + 63) / 64, (NNODES + 127) / 128);
    size_t smem = 2 * (ASZ + 2 * BSZ);
    k_mgemm<<<grid, 256, smem, st>>>(a, kpad,
                                     hWhi + (size_t)widx * 192 * 192,
                                     hWlo + (size_t)widx * 192 * 192,
                                     bias, out, ldc, M, nk, mode, half_out,
                                     NNODES);
}

static void mmdual(const __half* a, int kpad, int w1, int w2, int K,
                   const float* b1, const float* b2, const float* eps, int lde,
                   __half* out, int ldc, int M, cudaStream_t st) {
    int nk = (K + 31) / 32;
    dim3 grid((ldc + 63) / 64, (NNODES + 127) / 128);
    size_t smem = 2 * (ASZ + 4 * BSZ);
    k_mgemm_dual<<<grid, 256, smem, st>>>(a, kpad,
                                          hWhi + (size_t)w1 * 192 * 192,
                                          hWlo + (size_t)w1 * 192 * 192,
                                          hWhi + (size_t)w2 * 192 * 192,
                                          hWlo + (size_t)w2 * 192 * 192,
                                          b1, b2, eps, lde, out, ldc, M, nk,
                                          NNODES);
}

extern "C" void kernel_launch(void* const* d_in, const int* in_sizes, int n_in,
                              void* d_out, int out_size) {
    const float* x     = (const float*)d_in[0];
    const void*  ei    = d_in[1];
    const float* eps_e = (const float*)d_in[2];
    const float* eps_n = (const float*)d_in[3];
    const float* w1e = (const float*)d_in[4];  const float* b1e = (const float*)d_in[5];
    const float* w2e = (const float*)d_in[6];  const float* b2e = (const float*)d_in[7];
    const float* wme = (const float*)d_in[8];  const float* bme = (const float*)d_in[9];
    const float* wle = (const float*)d_in[10]; const float* ble = (const float*)d_in[11];
    const float* w4e = (const float*)d_in[12]; const float* b4e = (const float*)d_in[13];
    const float* w1n = (const float*)d_in[14]; const float* b1n = (const float*)d_in[15];
    const float* wmn = (const float*)d_in[16]; const float* bmn = (const float*)d_in[17];
    const float* wln = (const float*)d_in[18]; const float* bln = (const float*)d_in[19];
    const float* w5n = (const float*)d_in[20]; const float* b5n = (const float*)d_in[21];

    float* out   = (float*)d_out;
    float* edges = out;                         // [N,192]
    float* nodes = out + (size_t)NNODES * 192;  // [N,96]

    cudaGetSymbolAddress((void**)&hA, g_A);
    cudaGetSymbolAddress((void**)&hB, g_B);
    cudaGetSymbolAddress((void**)&hWhi, g_Whi);
    cudaGetSymbolAddress((void**)&hWlo, g_Wlo);
    cudaGetSymbolAddress((void**)&hactA, g_actA);
    cudaGetSymbolAddress((void**)&hactB, g_actB);
    cudaGetSymbolAddress((void**)&hactC, g_actC);

    cudaFuncSetAttribute(k_mgemm, cudaFuncAttributeMaxDynamicSharedMemorySize,
                         (int)(2 * (ASZ + 2 * BSZ)));
    cudaFuncSetAttribute(k_mgemm_dual,
                         cudaFuncAttributeMaxDynamicSharedMemorySize,
                         (int)(2 * (ASZ + 4 * BSZ)));

    cudaStream_t s0 = 0;
    cudaStream_t s1 = cudaStreamPerThread;
    cudaEvent_t evFork0, evDet, evPadx, evG1, evN1, evJoin;
    cudaEventCreateWithFlags(&evFork0, cudaEventDisableTiming);
    cudaEventCreateWithFlags(&evDet, cudaEventDisableTiming);
    cudaEventCreateWithFlags(&evPadx, cudaEventDisableTiming);
    cudaEventCreateWithFlags(&evG1, cudaEventDisableTiming);
    cudaEventCreateWithFlags(&evN1, cudaEventDisableTiming);
    cudaEventCreateWithFlags(&evJoin, cudaEventDisableTiming);

    // ---- fork: detect + weight split + x pad on s1; ideg zero on s0 ----
    cudaEventRecord(evFork0, s0);
    cudaStreamWaitEvent(s1, evFork0, 0);
    k_detect<<<512, 256, 0, s1>>>((const uint2*)ei);   // flag is replay-idempotent
    cudaEventRecord(evDet, s1);
    {
        WSet ws;
        ws.w[0] = w1e; ws.K[0] = 96;  ws.M[0] = 125;
        ws.w[1] = w2e; ws.K[1] = 125; ws.M[1] = 144;
        ws.w[2] = wme; ws.K[2] = 144; ws.M[2] = 163;
        ws.w[3] = wle; ws.K[3] = 144; ws.M[3] = 163;
        ws.w[4] = w4e; ws.K[4] = 163; ws.M[4] = 192;
        ws.w[5] = w1n; ws.K[5] = 96;  ws.M[5] = 96;
        ws.w[6] = wmn; ws.K[6] = 96;  ws.M[6] = 96;
        ws.w[7] = wln; ws.K[7] = 96;  ws.M[7] = 96;
        ws.w[8] = w5n; ws.K[8] = 96;  ws.M[8] = 96;
        dim3 g((192 * 192 + 255) / 256, 9);
        k_wsplit_all<<<g, 256, 0, s1>>>(ws, hWhi, hWlo);
    }
    k_padx<<<(NNODES * 128 + 255) / 256, 256, 0, s1>>>(x, hactB);
    cudaEventRecord(evPadx, s1);

    k_prep1<<<(NNODES + 255) / 256, 256, 0, s0>>>();
    cudaStreamWaitEvent(s0, evDet, 0);
    k_convert<<<(NEDGES + 255) / 256, 256, 0, s0>>>(ei);
    k_scanA<<<NBLK, 1024, 0, s0>>>();
    k_scanC<<<NBLK, 1024, 0, s0>>>();
    k_fill<<<(NEDGES + 255) / 256, 256, 0, s0>>>();

    // ---- shared first propagation: g1 = Â x (fp16) ----
    cudaStreamWaitEvent(s0, evPadx, 0);
    prop(hactB, 128, hA, s0);
    cudaEventRecord(evG1, s0);

    // ---- node branch on s1 (n1 reads g1's output hA) ----
    cudaStreamWaitEvent(s1, evG1, 0);
    mm(hA, 128, 5, 96, b1n, hactB, 128, 96, 1, 1, s1);          // n1 relu -> fp16
    cudaEventRecord(evN1, s1);
    prop(hactB, 128, hB, s1);                                   // g5
    mmdual(hB, 128, 6, 7, 96, bmn, bln, eps_n, 96,
           hactC, 128, 96, s1);                                 // nn -> fp16
    prop(hactC, 128, hB, s1);                                   // g6
    mm(hB, 128, 8, 96, b5n, nodes, 96, 96, 1, 0, s1);           // relu -> fp32 out

    // ---- edge branch on s0 ----
    mm(hA, 128, 0, 96, b1e, hactA, 128, 125, 1, 1, s0);         // e1 relu -> fp16
    cudaStreamWaitEvent(s0, evN1, 0);   // g2 overwrites hA; n1 must be done
    prop(hactA, 128, hA, s0);                                   // g2
    mm(hA, 128, 1, 125, b2e, hactA, 192, 144, 1, 1, s0);        // e2 relu -> fp16 (ldc192)
    prop(hactA, 192, hA, s0);                                   // g3
    mmdual(hA, 192, 2, 3, 144, bme, ble, eps_e, 163,
           hactA, 192, 163, s0);                                // e reparam -> fp16
    prop(hactA, 192, hA, s0);                                   // g4
    mm(hA, 192, 4, 163, b4e, edges, 192, 192, 2, 0, s0);        // sigmoid -> fp32 out

    // ---- join ----
    cudaEventRecord(evJoin, s1);
    cudaStreamWaitEvent(s0, evJoin, 0);
}